// round 16
// baseline (speedup 1.0000x reference)
#include <cuda_runtime.h>
#include <cuda_bf16.h>
#include <cuda_pipeline.h>

// CensoredLoss: outputs [B, T, V-1] f32, targets [B, T, V] f32, T=512, V=5.
// loss  = sum_{b,t} [ tgt0*log(1 - sum(out) + EPS) + sum_v tgt_{v+1}*log(out_v + EPS) ]
//         (masked rows have all-zero targets -> contribute exactly 0)
// count = #{(b,t) : sum_v targets[b,t,v] > 0}
// result = count > 0 ? -loss/count : 0
//
// Traffic: outputs loaded ONLY for valid records (~50%) -> ~235 MB total.
// Latency: two-phase record processing. Phase A computes all 4 validity
// flags from smem and issues the (predicated) outputs LDG.128s back-to-back
// -> 4 loads in flight instead of a serialized sum->ldg->log chain per
// record. Phase B re-reads targets from smem (cheap LDS) and does the math.
//
// SINGLE kernel, grid = nblocks+1, 256-thread blocks, 2 rows/block;
// workers end with fire-and-forget REDs + red.release ticket; finalizer
// block spin-acquires, writes out[0], resets state for the next replay.

#define T_DIM 512
#define V_DIM 5
#define RPB   2                           // rows per worker block
#define NREC  4                           // records per thread (RPB rows x 2 t-chunks)
#define ROW_FLOATS (T_DIM * V_DIM)        // 2560
#define EPSF  1e-8f
#define NTHREADS 256

__device__ double       g_loss;           // zero at module load; finalizer re-zeros
__device__ unsigned int g_count;
__device__ unsigned int g_ticket;

__global__ __launch_bounds__(NTHREADS, 8)
void cl_main_kernel(const float* __restrict__ outputs,
                    const float* __restrict__ targets,
                    float* __restrict__ out,
                    int nblocks)
{
    __shared__ float s_tgt[RPB * ROW_FLOATS];     // 20480 B, two rows of targets
    __shared__ float s_sum[NTHREADS / 32];
    __shared__ int   s_cnt[NTHREADS / 32];

    const int tid = threadIdx.x;

    // ---- Finalizer block (last in the grid, scheduled in the last wave) ----
    if (blockIdx.x == (unsigned)nblocks) {
        if (tid == 0) {
            unsigned int tk;
            for (;;) {
                asm volatile("ld.acquire.gpu.global.u32 %0, [%1];"
                             : "=r"(tk) : "l"(&g_ticket) : "memory");
                if (tk >= (unsigned int)nblocks) break;
                __nanosleep(128);
            }
            // Acquire synchronizes-with every worker's red.release.
            const double loss     = *((volatile double*)&g_loss);
            const unsigned int ct = *((volatile unsigned int*)&g_count);
            out[0] = (ct > 0u) ? (float)(-loss / (double)ct) : 0.0f;
            g_loss  = 0.0;
            g_count = 0u;
            *((volatile unsigned int*)&g_ticket) = 0u;
        }
        return;    // other threads exit immediately (no barrier in this block)
    }

    // ---- Worker blocks ----
    const int b0 = blockIdx.x * RPB;

    // Stage 2 rows of targets via cp.async (no register round-trip).
    {
        const float4* src = reinterpret_cast<const float4*>(
            targets + (size_t)b0 * ROW_FLOATS);
        float4* dst = reinterpret_cast<float4*>(s_tgt);
        #pragma unroll
        for (int i = tid; i < (RPB * ROW_FLOATS) / 4; i += NTHREADS)
            __pipeline_memcpy_async(&dst[i], &src[i], 16);
        __pipeline_commit();
    }
    __pipeline_wait_prior(0);
    __syncthreads();

    const float4* og4 = reinterpret_cast<const float4*>(outputs);

    // Phase A: validity flags for all 4 records + batched conditional LDGs.
    int    nzv[NREC];
    float4 ov[NREC];
    #pragma unroll
    for (int i = 0; i < NREC; i++) {
        const int r = i >> 1;
        const int t = tid + (i & 1) * 256;
        const float* q = s_tgt + r * ROW_FLOATS + t * 5;  // gcd(5,32)=1: conflict-free
        const float s = q[0] + q[1] + q[2] + q[3] + q[4];
        nzv[i] = (s > 0.0f);
        if (nzv[i])
            ov[i] = og4[(size_t)(b0 + r) * T_DIM + t];    // predicated LDG.128, batched
    }

    // Phase B: math (smem re-reads are cheap LDS hits).
    float c   = 0.0f;
    int   cnt = 0;
    #pragma unroll
    for (int i = 0; i < NREC; i++) {
        cnt += nzv[i];
        if (nzv[i]) {
            const int r = i >> 1;
            const int t = tid + (i & 1) * 256;
            const float* q = s_tgt + r * ROW_FLOATS + t * 5;
            const float t0 = q[0], t1 = q[1], t2 = q[2], t3 = q[3], t4 = q[4];
            const float4 o = ov[i];
            const float censor = 1.0f - (o.x + o.y + o.z + o.w);
            c += t0 * __logf(censor + EPSF)
               + t1 * __logf(o.x + EPSF)
               + t2 * __logf(o.y + EPSF)
               + t3 * __logf(o.z + EPSF)
               + t4 * __logf(o.w + EPSF);
        }
    }

    // Warp reduction.
    #pragma unroll
    for (int off = 16; off > 0; off >>= 1) {
        c   += __shfl_down_sync(0xffffffffu, c, off);
        cnt += __shfl_down_sync(0xffffffffu, cnt, off);
    }
    if ((tid & 31) == 0) {
        s_sum[tid >> 5] = c;
        s_cnt[tid >> 5] = cnt;
    }
    __syncthreads();

    // Final reduce across 8 warps (lanes 0..7 of warp 0), then fire-and-forget
    // REDs; the red.release ticket orders them for the finalizer's acquire.
    if (tid < NTHREADS / 32) {
        c   = s_sum[tid];
        cnt = s_cnt[tid];
        #pragma unroll
        for (int off = (NTHREADS / 64); off > 0; off >>= 1) {
            c   += __shfl_down_sync(0xffu, c, off);
            cnt += __shfl_down_sync(0xffu, cnt, off);
        }
        if (tid == 0) {
            atomicAdd(&g_loss, (double)c);           // RED.f64 (return unused)
            atomicAdd(&g_count, (unsigned int)cnt);  // RED.u32 (return unused)
            asm volatile("red.release.gpu.global.add.u32 [%0], %1;"
                         :: "l"(&g_ticket), "r"(1u) : "memory");
        }
    }
}

extern "C" void kernel_launch(void* const* d_in, const int* in_sizes, int n_in,
                              void* d_out, int out_size)
{
    const float* outputs = (const float*)d_in[0];
    const float* targets = (const float*)d_in[1];
    float* out = (float*)d_out;

    const int B       = in_sizes[1] / ROW_FLOATS;   // 16384
    const int nblocks = B / RPB;                    // 8192 worker blocks

    cl_main_kernel<<<nblocks + 1, NTHREADS>>>(outputs, targets, out, nblocks);
}

// round 17
// speedup vs baseline: 1.2521x; 1.2521x over previous
#include <cuda_runtime.h>
#include <cuda_bf16.h>
#include <cuda_pipeline.h>

// CensoredLoss: outputs [B, T, V-1] f32, targets [B, T, V] f32, T=512, V=5.
// loss  = sum_{b,t} [ tgt0*log(1 - sum(out) + EPS) + sum_v tgt_{v+1}*log(out_v + EPS) ]
//         (masked rows have all-zero targets -> contribute exactly 0)
// count = #{(b,t) : sum_v targets[b,t,v] > 0}
// result = count > 0 ? -loss/count : 0
//
// R13 structure (best measured) + pairwise conditional loads:
// per row, compute both validity flags from smem FIRST, then issue both
// predicated LDG.128s back-to-back (MLP 2, no indexed array -> no spills),
// then do the math for both records. Outputs read only for valid records
// (~50% of that stream skipped; skips warp-coherent via the prefix mask).
//
// SINGLE kernel, grid = nblocks+1, 256-thread blocks, 2 rows/block;
// workers end with fire-and-forget REDs + red.release ticket; finalizer
// block spin-acquires, writes out[0], resets state for the next replay.

#define T_DIM 512
#define V_DIM 5
#define RPB   2                           // rows per worker block
#define ROW_FLOATS (T_DIM * V_DIM)        // 2560
#define EPSF  1e-8f
#define NTHREADS 256

__device__ double       g_loss;           // zero at module load; finalizer re-zeros
__device__ unsigned int g_count;
__device__ unsigned int g_ticket;

__global__ __launch_bounds__(NTHREADS, 8)
void cl_main_kernel(const float* __restrict__ outputs,
                    const float* __restrict__ targets,
                    float* __restrict__ out,
                    int nblocks)
{
    __shared__ float s_tgt[RPB * ROW_FLOATS];     // 20480 B, two rows of targets
    __shared__ float s_sum[NTHREADS / 32];
    __shared__ int   s_cnt[NTHREADS / 32];

    const int tid = threadIdx.x;

    // ---- Finalizer block (last in the grid, scheduled in the last wave) ----
    if (blockIdx.x == (unsigned)nblocks) {
        if (tid == 0) {
            unsigned int tk;
            for (;;) {
                asm volatile("ld.acquire.gpu.global.u32 %0, [%1];"
                             : "=r"(tk) : "l"(&g_ticket) : "memory");
                if (tk >= (unsigned int)nblocks) break;
                __nanosleep(128);
            }
            // Acquire synchronizes-with every worker's red.release.
            const double loss     = *((volatile double*)&g_loss);
            const unsigned int ct = *((volatile unsigned int*)&g_count);
            out[0] = (ct > 0u) ? (float)(-loss / (double)ct) : 0.0f;
            g_loss  = 0.0;
            g_count = 0u;
            *((volatile unsigned int*)&g_ticket) = 0u;
        }
        return;    // other threads exit immediately (no barrier in this block)
    }

    // ---- Worker blocks ----
    const int b0 = blockIdx.x * RPB;

    // Stage 2 rows of targets via cp.async (no register round-trip).
    {
        const float4* src = reinterpret_cast<const float4*>(
            targets + (size_t)b0 * ROW_FLOATS);
        float4* dst = reinterpret_cast<float4*>(s_tgt);
        #pragma unroll
        for (int i = tid; i < (RPB * ROW_FLOATS) / 4; i += NTHREADS)
            __pipeline_memcpy_async(&dst[i], &src[i], 16);
        __pipeline_commit();
    }
    __pipeline_wait_prior(0);
    __syncthreads();

    const float4* og4 = reinterpret_cast<const float4*>(outputs);
    float c   = 0.0f;
    int   cnt = 0;

    // Per row: both t-chunks together. Flags first, then BOTH predicated
    // LDG.128s back-to-back (explicit scalars -> register-resident), then math.
    #pragma unroll
    for (int r = 0; r < RPB; r++) {
        const int ta = tid;
        const int tb = tid + 256;
        const float* qa = s_tgt + r * ROW_FLOATS + ta * 5;  // gcd(5,32)=1: conflict-free
        const float* qb = s_tgt + r * ROW_FLOATS + tb * 5;

        const float a0 = qa[0], a1 = qa[1], a2 = qa[2], a3 = qa[3], a4 = qa[4];
        const float b0f = qb[0], b1 = qb[1], b2 = qb[2], b3 = qb[3], b4 = qb[4];

        const int nza = ((a0 + a1 + a2 + a3 + a4) > 0.0f);
        const int nzb = ((b0f + b1 + b2 + b3 + b4) > 0.0f);
        cnt += nza + nzb;

        float4 oa, ob;
        if (nza) oa = og4[(size_t)(b0 + r) * T_DIM + ta];   // predicated, issued
        if (nzb) ob = og4[(size_t)(b0 + r) * T_DIM + tb];   // back-to-back (MLP 2)

        if (nza) {
            const float censor = 1.0f - (oa.x + oa.y + oa.z + oa.w);
            c += a0 * __logf(censor + EPSF)
               + a1 * __logf(oa.x + EPSF)
               + a2 * __logf(oa.y + EPSF)
               + a3 * __logf(oa.z + EPSF)
               + a4 * __logf(oa.w + EPSF);
        }
        if (nzb) {
            const float censor = 1.0f - (ob.x + ob.y + ob.z + ob.w);
            c += b0f * __logf(censor + EPSF)
               + b1  * __logf(ob.x + EPSF)
               + b2  * __logf(ob.y + EPSF)
               + b3  * __logf(ob.z + EPSF)
               + b4  * __logf(ob.w + EPSF);
        }
    }

    // Warp reduction.
    #pragma unroll
    for (int off = 16; off > 0; off >>= 1) {
        c   += __shfl_down_sync(0xffffffffu, c, off);
        cnt += __shfl_down_sync(0xffffffffu, cnt, off);
    }
    if ((tid & 31) == 0) {
        s_sum[tid >> 5] = c;
        s_cnt[tid >> 5] = cnt;
    }
    __syncthreads();

    // Final reduce across 8 warps (lanes 0..7 of warp 0), then fire-and-forget
    // REDs; the red.release ticket orders them for the finalizer's acquire.
    if (tid < NTHREADS / 32) {
        c   = s_sum[tid];
        cnt = s_cnt[tid];
        #pragma unroll
        for (int off = (NTHREADS / 64); off > 0; off >>= 1) {
            c   += __shfl_down_sync(0xffu, c, off);
            cnt += __shfl_down_sync(0xffu, cnt, off);
        }
        if (tid == 0) {
            atomicAdd(&g_loss, (double)c);           // RED.f64 (return unused)
            atomicAdd(&g_count, (unsigned int)cnt);  // RED.u32 (return unused)
            asm volatile("red.release.gpu.global.add.u32 [%0], %1;"
                         :: "l"(&g_ticket), "r"(1u) : "memory");
        }
    }
}

extern "C" void kernel_launch(void* const* d_in, const int* in_sizes, int n_in,
                              void* d_out, int out_size)
{
    const float* outputs = (const float*)d_in[0];
    const float* targets = (const float*)d_in[1];
    float* out = (float*)d_out;

    const int B       = in_sizes[1] / ROW_FLOATS;   // 16384
    const int nblocks = B / RPB;                    // 8192 worker blocks

    cl_main_kernel<<<nblocks + 1, NTHREADS>>>(outputs, targets, out, nblocks);
}